// round 7
// baseline (speedup 1.0000x reference)
#include <cuda_runtime.h>
#include <math.h>

// Problem constants
#define NS 4096
#define NT 4096
#define NVEC (NT/4)          // 1024 float4 per row
#define RBLK 16              // rows per pde block
#define GY (NS/RBLK)         // 256 row tiles
#define GX 4                 // column tiles (4 * 256 threads * 4 floats = 4096 cols)
#define TPB 256
#define NB_PDE (GX*GY)       // 1024 pde blocks
#define NB_BT 8              // boundary/terminal blocks
#define NB_TOTAL (NB_PDE + NB_BT)   // 1032 <= 148*7 = 1036 -> single wave

// Residual is computed scaled by 2*DT_NORM (vt needs no multiply); block sums
// are un-scaled once by INV2DT^2 = 102375^2 in double.
#define S2DT  (9.76800976800976801e-6)   // 2*DT_NORM = 0.04/4095
#define INV2DT2_D (10480640625.0)        // 102375^2

// Scratch (no allocations allowed anywhere)
static __device__ double g_pde[NB_PDE];
static __device__ double g_bc[NB_BT];
static __device__ double g_tc[NB_BT];
static __device__ int    g_count = 0;

// Faithful port of CubicStretching._solve_depressed_cubic (hyperbolic form)
__device__ __forceinline__ float cubic_root(float Q) {
    const float p  = 6.0f;                       // CHI
    const float sp = 2.4494897427831781f;        // sqrt(6)
    float q = p * Q;                             // CHI * Q
    const float den = 2.0f * p * sp / (3.0f * 1.7320508075688772f); // = 4*sqrt(2)
    float arg = fabsf(q) / den;
    arg = fmaxf(arg, 1.0f);
    float c = 2.0f * sp * coshf(acoshf(arg) / 3.0f);
    return (q >= 0.0f) ? -c : c;
}

// Per-row stencil coefficients (reference chain rule; x/w pre-scaled by 2*DT)
__device__ __forceinline__ float4 row_coef(int i) {
    float C1 = cubic_root(100.0f / 30.0f);       // (B - 0)/ALPHA_STR
    float C2 = cubic_root(-200.0f / 30.0f);      // (B - S_MAX)/ALPHA_STR
    float u   = (float)i * (1.0f / 4095.0f);
    float L   = C2 * u + C1 * (1.0f - u);
    float dL  = C2 - C1;
    float S   = 100.0f + 30.0f * (L * L * L * (1.0f / 6.0f) + L);
    float Su  = 30.0f * dL * (0.5f * L * L + 1.0f);
    float Suu = 30.0f * dL * dL * L;
    float Sn   = S   * (1.0f / 300.0f);
    float Sun  = Su  * (1.0f / 300.0f);
    float Suun = Suu * (1.0f / 300.0f);
    const float INV2DU = 2047.5f;                // 1/(2*DU), DU = 1/4095
    const float INVDU2 = 16769025.0f;            // 1/DU^2 = 4095^2
    float is = 1.0f / Sun;
    float4 c;
    c.x = Sn * Sn * (float)S2DT;                 // scaled V_SS multiplier
    c.y = INVDU2 * is * is;                      // duu coefficient inside raw V_SS
    c.z = INV2DU * Suun * is * is * is;          // du coefficient inside raw V_SS
    c.w = 2.5f * Sn * INV2DU * is * (float)S2DT; // scaled advection coefficient
    return c;
}

__global__ void __launch_bounds__(TPB, 7) fused_kernel(const float* __restrict__ V,
                                                       float* __restrict__ out) {
    __shared__ float4 scoef[RBLK];
    __shared__ double sred[TPB / 32 > 8 ? TPB / 32 : 8];

    const int b   = blockIdx.x;
    const int tid = threadIdx.x;
    const int w   = tid >> 5, l = tid & 31;

    if (b < NB_PDE) {
        // ------------------- PDE residual tile -------------------
        const int gx = b & (GX - 1);
        const int gy = b >> 2;
        const int rb = gy * RBLK;

        if (tid < RBLK) scoef[tid] = row_coef(rb + tid);
        __syncthreads();

        const float C25 = 2.5f * (float)S2DT;    // scaled ALPHA*V coefficient
        const int jv = gx * TPB + tid;           // float4 column 0..1023
        const bool hasL = (jv != 0);             // k=0 term included iff j0-1 exists
        const bool hasR = (jv != NVEC - 1);      // k=3 term included iff j0+4 exists
        // interior rows of this tile: [rlo, rhi)
        const int rlo = (gy == 0) ? 1 : rb;
        const int rhi = (gy == GY - 1) ? NS - 1 : rb + RBLK;
        const int nrows = rhi - rlo;

        // Warp-edge halo preload: lanes 0..15 hold left halos for rows rlo+lr,
        // lanes 16..31 hold right halos. One strided warp-wide LDG, no per-row loads.
        const int j0w  = gx * 1024 + ((tid >> 5) << 7);   // warp's first scalar column
        const int side = l >> 4;
        const int lr   = l & 15;
        const int hcol = side ? (j0w + 128) : (j0w - 1);
        const bool hok = (lr < nrows) && (hcol >= 0) && (hcol < NT);
        float halo = hok ? V[(size_t)(rlo + lr) * NT + hcol] : 0.0f;

        const float4* __restrict__ p = (const float4*)V + (size_t)rlo * NVEC + jv;
        float4 prev = p[-NVEC];
        float4 cur  = p[0];

        float acc = 0.0f;
        #pragma unroll 8
        for (int r = rlo; r < rhi; ++r) {
            float4 nxt = p[NVEC];
            p += NVEC;
            const int idx = r - rlo;
            // neighbor values via warp shuffle; warp-edge lanes patch from halo reg
            float leftv  = __shfl_up_sync(0xffffffffu,  cur.w, 1);
            float rightv = __shfl_down_sync(0xffffffffu, cur.x, 1);
            float lb  = __shfl_sync(0xffffffffu, halo, idx);
            float rb2 = __shfl_sync(0xffffffffu, halo, 16 + idx);
            if (l == 0)  leftv  = lb;
            if (l == 31) rightv = rb2;
            float4 cf = scoef[r - rb];

            {   // k = 0  (scaled residual: vt term needs no multiply)
                float du  = nxt.x - prev.x;
                float duu = nxt.x - 2.0f * cur.x + prev.x;
                float vss = fminf(fmaxf(duu * cf.y - du * cf.z, -100.0f), 100.0f);
                float res = (cur.y - leftv) - cf.x * vss - cf.w * du + C25 * cur.x;
                if (hasL) acc = fmaf(res, res, acc);
            }
            {   // k = 1
                float du  = nxt.y - prev.y;
                float duu = nxt.y - 2.0f * cur.y + prev.y;
                float vss = fminf(fmaxf(duu * cf.y - du * cf.z, -100.0f), 100.0f);
                float res = (cur.z - cur.x) - cf.x * vss - cf.w * du + C25 * cur.y;
                acc = fmaf(res, res, acc);
            }
            {   // k = 2
                float du  = nxt.z - prev.z;
                float duu = nxt.z - 2.0f * cur.z + prev.z;
                float vss = fminf(fmaxf(duu * cf.y - du * cf.z, -100.0f), 100.0f);
                float res = (cur.w - cur.y) - cf.x * vss - cf.w * du + C25 * cur.z;
                acc = fmaf(res, res, acc);
            }
            {   // k = 3
                float du  = nxt.w - prev.w;
                float duu = nxt.w - 2.0f * cur.w + prev.w;
                float vss = fminf(fmaxf(duu * cf.y - du * cf.z, -100.0f), 100.0f);
                float res = (rightv - cur.z) - cf.x * vss - cf.w * du + C25 * cur.w;
                if (hasR) acc = fmaf(res, res, acc);
            }
            prev = cur; cur = nxt;
        }

        // deterministic block reduce -> double partial (un-scale by INV2DT^2)
        #pragma unroll
        for (int o = 16; o; o >>= 1) acc += __shfl_down_sync(0xffffffffu, acc, o);
        __syncthreads();                          // sred reuse barrier vs scoef
        if (l == 0) sred[w] = (double)acc;
        __syncthreads();
        if (tid == 0) {
            double s = 0.0;
            #pragma unroll
            for (int k = 0; k < TPB / 32; k++) s += sred[k];
            g_pde[b] = s * INV2DT2_D;
        }
    } else {
        // ------------------- BC (row NS-1) + terminal (col NT-1) -------------------
        const int kb = b - NB_PDE;                // 0..7
        float bcv = 0.0f, tcv = 0.0f;
        #pragma unroll
        for (int e = 0; e < 2; ++e) {
            int i = kb * 512 + e * 256 + tid;     // 0..4095
            float u = (float)i * (1.0f / 4095.0f);

            // BC at S = S_max (t[j] = j/4095 == u here)
            float tgt = 1.0f - (100.0f / 300.0f) * expf(-0.05f * (1.0f - u));
            float db  = V[(size_t)(NS - 1) * NT + i] - tgt;
            bcv += db * db;

            // Terminal softplus payoff + Huber
            float x = 50.0f * (u - (100.0f / 300.0f));
            float payoff = (fmaxf(x, 0.0f) + log1pf(expf(-fabsf(x)))) * 0.02f;
            float dd = V[(size_t)i * NT + (NT - 1)] - payoff;
            float ad = fabsf(dd);
            tcv += (ad < 0.01f) ? 0.5f * dd * dd : 0.01f * (ad - 0.005f);
        }
        #pragma unroll
        for (int o = 16; o; o >>= 1) {
            bcv += __shfl_down_sync(0xffffffffu, bcv, o);
            tcv += __shfl_down_sync(0xffffffffu, tcv, o);
        }
        __shared__ float sb[TPB / 32], st[TPB / 32];
        if (l == 0) { sb[w] = bcv; st[w] = tcv; }
        __syncthreads();
        if (tid == 0) {
            double B = 0.0, T = 0.0;
            #pragma unroll
            for (int k = 0; k < TPB / 32; k++) { B += (double)sb[k]; T += (double)st[k]; }
            g_bc[kb] = B;
            g_tc[kb] = T;
        }
    }

    // ------------------- last block finalizes -------------------
    __shared__ bool is_last;
    __threadfence();
    if (tid == 0) {
        int prev_cnt = atomicAdd(&g_count, 1);
        is_last = (prev_cnt == NB_TOTAL - 1);
    }
    __syncthreads();
    if (!is_last) return;

    __threadfence();
    volatile double* vpde = g_pde;
    volatile double* vbc  = g_bc;
    volatile double* vtc  = g_tc;

    double v = 0.0;
    for (int k = tid; k < NB_PDE; k += TPB) v += vpde[k];
    double bc = (tid < NB_BT) ? vbc[tid] : 0.0;
    double tc = (tid < NB_BT) ? vtc[tid] : 0.0;

    __shared__ double fp[TPB / 32], fb[TPB / 32], ft[TPB / 32];
    #pragma unroll
    for (int o = 16; o; o >>= 1) {
        v  += __shfl_down_sync(0xffffffffu, v, o);
        bc += __shfl_down_sync(0xffffffffu, bc, o);
        tc += __shfl_down_sync(0xffffffffu, tc, o);
    }
    __syncthreads();
    if (l == 0) { fp[w] = v; fb[w] = bc; ft[w] = tc; }
    __syncthreads();
    if (tid == 0) {
        double P = 0.0, B = 0.0, T = 0.0;
        #pragma unroll
        for (int k = 0; k < TPB / 32; k++) { P += fp[k]; B += fb[k]; T += ft[k]; }
        const double n_int = 4094.0 * 4094.0;
        out[0] = (float)(P / n_int + 10.0 * (B / 4096.0) + 10.0 * (T / 4096.0));
        g_count = 0;                              // self-reset for next graph replay
    }
}

extern "C" void kernel_launch(void* const* d_in, const int* in_sizes, int n_in,
                              void* d_out, int out_size) {
    const float* V = (const float*)d_in[0];
    float* out = (float*)d_out;
    fused_kernel<<<NB_TOTAL, TPB>>>(V, out);
}